// round 5
// baseline (speedup 1.0000x reference)
#include <cuda_runtime.h>

#define BB   8
#define CIN  32
#define COUT 32
#define HH   128
#define WW   128
#define SS   1024
#define JJ   (HH*WW)
#define NB   256          // 2 CTAs/SM capacity on 148 SMs -> all co-resident
#define NT   256
#define GRP  32           // blocks per batch group

// Scratch (fully overwritten every launch) + monotone per-batch barrier
// counters (never reset; each launch adds exactly GRP to each, so epoch
// targets are multiples of GRP).
__device__ float g_T[BB*CIN];
__device__ float g_U[BB*CIN];
__device__ float g_V[BB*CIN];
__device__ unsigned int g_barB[BB];   // zero-initialized at module load

__global__ void __launch_bounds__(NT) nystrom_fused(
    const float* __restrict__ v,        // [B, CIN, H, W]
    const float* __restrict__ weight,   // [COUT, CIN, 2]
    const int*   __restrict__ idx32,    // int32 or int64 (detected)
    float*       __restrict__ out)      // [B, COUT, H, W]
{
    const int tid  = threadIdx.x;
    const int lane = tid & 31;
    const int warp = tid >> 5;
    const float step = 2.0f / 127.0f;

    // indices are a permutation (distinct); three zeros at int32 positions
    // 1,3,5 can only be int64 high-halves.
    const bool is64 = (idx32[1] == 0) && (idx32[3] == 0) && (idx32[5] == 0);

    __shared__ float sred[3][8];

    const int bi = blockIdx.x;           // b*32 + i  (phase 1 task)
    const int b  = bi >> 5;
    const int o  = bi & 31;              // phase 2 plane: same (b, o=i)

    // ---------- Phase 1: gather-reduce T/U/V for ONE (b,i) -------------------
    {
        const float* plane = v + (size_t)bi * JJ;

        float t = 0.f, u = 0.f, w = 0.f;
        #pragma unroll
        for (int k = 0; k < 4; ++k) {
            const int s = tid + k * NT;
            const int j = is64 ? idx32[2 * s] : idx32[s];
            const float x = -1.0f + step * (float)(j & (WW - 1));
            const float y = -1.0f + step * (float)(j >> 7);
            const float val = __ldg(plane + j);
            t += val;
            u  = fmaf(x, val, u);
            w  = fmaf(y, val, w);
        }
        #pragma unroll
        for (int off = 16; off > 0; off >>= 1) {
            t += __shfl_down_sync(0xffffffffu, t, off);
            u += __shfl_down_sync(0xffffffffu, u, off);
            w += __shfl_down_sync(0xffffffffu, w, off);
        }
        if (lane == 0) { sred[0][warp] = t; sred[1][warp] = u; sred[2][warp] = w; }
        __syncthreads();
        if (warp == 0) {                 // shuffle-reduce 8 partials in warp 0
            float T = (lane < 8) ? sred[0][lane] : 0.f;
            float U = (lane < 8) ? sred[1][lane] : 0.f;
            float V = (lane < 8) ? sred[2][lane] : 0.f;
            #pragma unroll
            for (int off = 4; off > 0; off >>= 1) {
                T += __shfl_down_sync(0xffffffffu, T, off);
                U += __shfl_down_sync(0xffffffffu, U, off);
                V += __shfl_down_sync(0xffffffffu, V, off);
            }
            if (lane == 0) { g_T[bi] = T; g_U[bi] = U; g_V[bi] = V; }
        }
    }

    // Weight preload (independent of phase 1 -> overlaps the barrier wait).
    const float2 wv = ((const float2*)weight)[o * CIN + lane];

    // ---------- Per-batch barrier (epoch-based, replay-safe) ------------------
    // Arrive: one atomic per block. Poll: plain volatile L2 reads (no atomic
    // ALU serialization).
    if (tid == 0) {
        __threadfence();                                    // release T/U/V[b,*]
        volatile unsigned int* bar = (volatile unsigned int*)&g_barB[b];
        const unsigned int old = atomicAdd(&g_barB[b], 1u);
        const unsigned int target = (old / GRP + 1u) * GRP; // end of this epoch
        while (*bar < target) { __nanosleep(32); }
        __threadfence();                                    // acquire
    }
    __syncthreads();

    // ---------- Phase 2: fill ONE output plane (b,o) --------------------------
    {
        // Warp-parallel dot: lane = channel. L2-only loads (skip stale L1).
        const float T = __ldcg(g_T + b * CIN + lane);
        const float U = __ldcg(g_U + b * CIN + lane);
        const float V = __ldcg(g_V + b * CIN + lane);

        float p = T * wv.x;
        float q = T * wv.y;
        float r = fmaf(U, wv.x, V * wv.y);
        #pragma unroll
        for (int off = 16; off > 0; off >>= 1) {
            p += __shfl_xor_sync(0xffffffffu, p, off);
            q += __shfl_xor_sync(0xffffffffu, q, off);
            r += __shfl_xor_sync(0xffffffffu, r, off);
        }
        const float P = p, Q = q, R = r;

        float4* outp = (float4*)(out + (size_t)bi * JJ);
        #pragma unroll
        for (int k = 0; k < 16; ++k) {
            const int q4 = tid + k * NT;           // float4 index in plane [0,4096)
            const int h  = q4 >> 5;
            const int wq = (q4 * 4) & (WW - 1);
            const float y = -1.0f + step * (float)h;
            const float base = fmaf(y, Q, -R);
            const float x0 = -1.0f + step * (float)wq;
            float4 o4;
            o4.x = fmaf(x0,               P, base);
            o4.y = fmaf(x0 +        step, P, base);
            o4.z = fmaf(x0 + 2.0f * step, P, base);
            o4.w = fmaf(x0 + 3.0f * step, P, base);
            outp[q4] = o4;
        }
    }
}

extern "C" void kernel_launch(void* const* d_in, const int* in_sizes, int n_in,
                              void* d_out, int out_size)
{
    const float* v      = (const float*)d_in[0];
    const float* weight = (const float*)d_in[1];
    const int*   idx32  = (const int*)  d_in[2];
    float*       out    = (float*)d_out;

    nystrom_fused<<<NB, NT>>>(v, weight, idx32, out);
}

// round 6
// speedup vs baseline: 1.1493x; 1.1493x over previous
#include <cuda_runtime.h>

#define BB   8
#define CIN  32
#define COUT 32
#define HH   128
#define WW   128
#define SS   1024
#define JJ   (HH*WW)

// Scratch: fully overwritten every launch (deterministic across graph replays).
__device__ float g_T[BB*CIN];
__device__ float g_U[BB*CIN];
__device__ float g_V[BB*CIN];

// ---------------------------------------------------------------------------
// Kernel A: one block per (b,i). T/U/V gather-reductions.
// Triggers programmatic launch completion so the PDL-launched fill kernel
// can proceed the moment these results are visible.
// ---------------------------------------------------------------------------
__global__ void __launch_bounds__(256) nystrom_reduce_tuv(
    const float* __restrict__ v,
    const int*   __restrict__ idx32)   // int32 or int64 (detected)
{
    const int bi  = blockIdx.x;            // b*32 + i
    const float* plane = v + (size_t)bi * JJ;
    const int tid  = threadIdx.x;
    const int lane = tid & 31;
    const int warp = tid >> 5;

    // indices are a permutation (distinct); three zeros at int32 positions
    // 1,3,5 can only be int64 high-halves.
    const bool is64 = (idx32[1] == 0) && (idx32[3] == 0) && (idx32[5] == 0);

    const float step = 2.0f / 127.0f;
    float t = 0.f, u = 0.f, w = 0.f;

    #pragma unroll
    for (int k = 0; k < 4; ++k) {
        const int s = tid + k * 256;
        const int j = is64 ? idx32[2 * s] : idx32[s];
        const float x = -1.0f + step * (float)(j & (WW - 1));
        const float y = -1.0f + step * (float)(j >> 7);
        const float val = __ldg(plane + j);
        t += val;
        u  = fmaf(x, val, u);
        w  = fmaf(y, val, w);
    }

    #pragma unroll
    for (int off = 16; off > 0; off >>= 1) {
        t += __shfl_down_sync(0xffffffffu, t, off);
        u += __shfl_down_sync(0xffffffffu, u, off);
        w += __shfl_down_sync(0xffffffffu, w, off);
    }
    __shared__ float sred[3][8];
    if (lane == 0) { sred[0][warp] = t; sred[1][warp] = u; sred[2][warp] = w; }
    __syncthreads();
    if (warp == 0) {
        float T = (lane < 8) ? sred[0][lane] : 0.f;
        float U = (lane < 8) ? sred[1][lane] : 0.f;
        float V = (lane < 8) ? sred[2][lane] : 0.f;
        #pragma unroll
        for (int off = 4; off > 0; off >>= 1) {
            T += __shfl_down_sync(0xffffffffu, T, off);
            U += __shfl_down_sync(0xffffffffu, U, off);
            V += __shfl_down_sync(0xffffffffu, V, off);
        }
        if (lane == 0) { g_T[bi] = T; g_U[bi] = U; g_V[bi] = V; }
    }
    __syncthreads();

#if defined(__CUDA_ARCH__) && (__CUDA_ARCH__ >= 900)
    __threadfence();                                // make T/U/V globally visible
    cudaTriggerProgrammaticLaunchCompletion();      // release dependent grid
#endif
}

// ---------------------------------------------------------------------------
// Kernel B: output fill (R2 config: 4 blocks/plane, 4 float4 per thread).
// Launched with programmatic stream serialization: the entire ramp (CTA
// dispatch, weight loads, setup) overlaps kernel A; blocks wait on the
// grid dependency only right before consuming T/U/V.
// ---------------------------------------------------------------------------
__global__ void __launch_bounds__(256) nystrom_fill(
    const float* __restrict__ weight,   // [COUT, CIN, 2]
    float*       __restrict__ out)      // [B, COUT, H, W]
{
    const int plane = blockIdx.x >> 2;   // b*32 + o
    const int chunk = blockIdx.x & 3;    // 4096-float chunk within plane
    const int b = plane >> 5;
    const int o = plane & 31;
    const int tid  = threadIdx.x;
    const int lane = tid & 31;

    // Weight load + setup: independent of kernel A -> overlaps it.
    const float2 wv = ((const float2*)weight)[o * CIN + lane];
    const float step = 2.0f / 127.0f;

#if defined(__CUDA_ARCH__) && (__CUDA_ARCH__ >= 900)
    cudaGridDependencySynchronize();     // wait for kernel A's results
#endif

    // Warp-parallel dot: lane = channel. L2 loads (bypass possibly-stale L1).
    const float T = __ldcg(g_T + b * CIN + lane);
    const float U = __ldcg(g_U + b * CIN + lane);
    const float V = __ldcg(g_V + b * CIN + lane);

    float p = T * wv.x;
    float q = T * wv.y;
    float r = fmaf(U, wv.x, V * wv.y);
    #pragma unroll
    for (int off = 16; off > 0; off >>= 1) {
        p += __shfl_xor_sync(0xffffffffu, p, off);
        q += __shfl_xor_sync(0xffffffffu, q, off);
        r += __shfl_xor_sync(0xffffffffu, r, off);
    }
    const float P = p, Q = q, R = r;

    float4* outp = (float4*)(out + (size_t)plane * JJ + chunk * 4096);

    #pragma unroll
    for (int k = 0; k < 4; ++k) {
        const int q4 = tid + k * 256;          // float4 index within chunk
        const int rr = chunk * 4096 + q4 * 4;  // linear index within plane
        const int h  = rr >> 7;
        const int wq = rr & (WW - 1);
        const float y = -1.0f + step * (float)h;
        const float base = fmaf(y, Q, -R);
        const float x0 = -1.0f + step * (float)wq;
        float4 o4;
        o4.x = fmaf(x0,               P, base);
        o4.y = fmaf(x0 +        step, P, base);
        o4.z = fmaf(x0 + 2.0f * step, P, base);
        o4.w = fmaf(x0 + 3.0f * step, P, base);
        outp[q4] = o4;
    }
}

extern "C" void kernel_launch(void* const* d_in, const int* in_sizes, int n_in,
                              void* d_out, int out_size)
{
    const float* v      = (const float*)d_in[0];
    const float* weight = (const float*)d_in[1];
    const int*   idx32  = (const int*)  d_in[2];
    float*       out    = (float*)d_out;

    nystrom_reduce_tuv<<<BB * CIN, 256>>>(v, idx32);

    // PDL launch: fill kernel may start while reduce is running; it self-
    // synchronizes via cudaGridDependencySynchronize().
    cudaLaunchConfig_t cfg = {};
    cfg.gridDim  = dim3(BB * COUT * 4);
    cfg.blockDim = dim3(256);
    cfg.dynamicSmemBytes = 0;
    cfg.stream = 0;
    cudaLaunchAttribute attr[1];
    attr[0].id = cudaLaunchAttributeProgrammaticStreamSerialization;
    attr[0].val.programmaticStreamSerializationAllowed = 1;
    cfg.attrs = attr;
    cfg.numAttrs = 1;
    cudaLaunchKernelEx(&cfg, nystrom_fill, weight, (float*)out);
}